// round 13
// baseline (speedup 1.0000x reference)
#include <cuda_runtime.h>
#include <cstdint>

#define NN 100000
#define NE 1600000
#define BN_EPS 1e-5f

// ---------------- device scratch (no allocations allowed) ----------------
__device__ __align__(16) float g_p[NN * 64];     // x @ (W0_top - W0_bot) * s0
__device__ __align__(16) float g_q[NN * 64];     // x @ W0_bot * s0
__device__ __align__(16) float g_seg[NN * 64];   // segment sums
__device__ __align__(16) float g_cnt[NN];        // edge counts per dst
__device__ __align__(16) float g_z[NN * 128];    // y @ We0 per node
__device__ __align__(16) float g_w0a[16 * 64];
__device__ __align__(16) float g_w0b[16 * 64];
__device__ __align__(16) float g_W1[64 * 64];
__device__ __align__(16) float g_W2[64 * 64];
__device__ __align__(16) float g_B[3 * 64];      // folded biases B0,B1,B2

// ---------------- K0: fold BN into weights ----------------
__global__ void fold_kernel(
    const float* __restrict__ w0, const float* __restrict__ b0,
    const float* __restrict__ g0, const float* __restrict__ be0,
    const float* __restrict__ m0, const float* __restrict__ v0,
    const float* __restrict__ w1, const float* __restrict__ b1,
    const float* __restrict__ g1, const float* __restrict__ be1,
    const float* __restrict__ m1, const float* __restrict__ v1,
    const float* __restrict__ w2, const float* __restrict__ b2,
    const float* __restrict__ g2, const float* __restrict__ be2,
    const float* __restrict__ m2, const float* __restrict__ v2) {
  int j = threadIdx.x;  // 0..63
  float s0 = g0[j] * rsqrtf(v0[j] + BN_EPS);
  g_B[j] = (b0[j] - m0[j]) * s0 + be0[j];
  for (int i = 0; i < 16; i++) {
    float top = w0[i * 64 + j];
    float bot = w0[(16 + i) * 64 + j];
    g_w0a[i * 64 + j] = (top - bot) * s0;  // coefficient of x[dst]
    g_w0b[i * 64 + j] = bot * s0;          // coefficient of x[src]
  }
  float s1 = g1[j] * rsqrtf(v1[j] + BN_EPS);
  g_B[64 + j] = (b1[j] - m1[j]) * s1 + be1[j];
  for (int i = 0; i < 64; i++) g_W1[i * 64 + j] = w1[i * 64 + j] * s1;
  float s2 = g2[j] * rsqrtf(v2[j] + BN_EPS);
  g_B[128 + j] = (b2[j] - m2[j]) * s2 + be2[j];
  for (int i = 0; i < 64; i++) g_W2[i * 64 + j] = w2[i * 64 + j] * s2;
}

// ---------------- K1: per-node p,q precompute ----------------
// blockDim (64, 4): 4 nodes per block, thread j computes p[n][j], q[n][j]
__global__ void pq_kernel(const float* __restrict__ x) {
  int n = blockIdx.x * 4 + threadIdx.y;
  if (n >= NN) return;
  int j = threadIdx.x;
  float p = 0.f, q = 0.f;
#pragma unroll
  for (int i = 0; i < 16; i++) {
    float xi = __ldg(&x[n * 16 + i]);
    p = fmaf(xi, g_w0a[i * 64 + j], p);
    q = fmaf(xi, g_w0b[i * 64 + j], q);
  }
  g_p[n * 64 + j] = p;
  g_q[n * 64 + j] = q;
}

// ---------------- K2: per-edge MLP (layers 0..2) + atomic scatter ----------------
// 128 threads/block, 1 edge per thread. h lives in shared (stride-128, conflict-free),
// acc[64] in registers, weights broadcast from shared.
__global__ void __launch_bounds__(128) edge_mlp_kernel(const int* __restrict__ ei) {
  extern __shared__ float sm[];
  float* sW1 = sm;                 // 4096
  float* sW2 = sm + 4096;          // 4096
  float* sB = sm + 8192;           // 192
  float* sH = sm + 8192 + 192;     // 64 * 128

  int tid = threadIdx.x;
  for (int i = tid; i < 4096; i += 128) {
    sW1[i] = g_W1[i];
    sW2[i] = g_W2[i];
  }
  if (tid < 64) {
    sB[tid] = g_B[tid];
    sB[64 + tid] = g_B[64 + tid];
    sB[128 + tid] = g_B[128 + tid];
  }
  __syncthreads();

  int e = blockIdx.x * 128 + tid;
  if (e >= NE) return;
  int s = ei[e];
  int d = ei[NE + e];

  // layer 0: p[dst] + q[src] + B0, relu -> sH
  const float4* pd = (const float4*)(g_p + (size_t)d * 64);
  const float4* qs = (const float4*)(g_q + (size_t)s * 64);
  const float4* bb0 = (const float4*)sB;
#pragma unroll
  for (int jj = 0; jj < 16; jj++) {
    float4 a = pd[jj];
    float4 b = qs[jj];
    float4 c = bb0[jj];
    sH[(4 * jj + 0) * 128 + tid] = fmaxf(a.x + b.x + c.x, 0.f);
    sH[(4 * jj + 1) * 128 + tid] = fmaxf(a.y + b.y + c.y, 0.f);
    sH[(4 * jj + 2) * 128 + tid] = fmaxf(a.z + b.z + c.z, 0.f);
    sH[(4 * jj + 3) * 128 + tid] = fmaxf(a.w + b.w + c.w, 0.f);
  }

  float acc[64];

  // layer 1
#pragma unroll
  for (int j = 0; j < 64; j++) acc[j] = sB[64 + j];
#pragma unroll 2
  for (int k = 0; k < 64; k++) {
    float hk = sH[k * 128 + tid];
    const float4* wr = (const float4*)(sW1 + k * 64);
#pragma unroll
    for (int jj = 0; jj < 16; jj++) {
      float4 w = wr[jj];
      acc[4 * jj + 0] = fmaf(hk, w.x, acc[4 * jj + 0]);
      acc[4 * jj + 1] = fmaf(hk, w.y, acc[4 * jj + 1]);
      acc[4 * jj + 2] = fmaf(hk, w.z, acc[4 * jj + 2]);
      acc[4 * jj + 3] = fmaf(hk, w.w, acc[4 * jj + 3]);
    }
  }
#pragma unroll
  for (int k = 0; k < 64; k++) sH[k * 128 + tid] = fmaxf(acc[k], 0.f);

  // layer 2
#pragma unroll
  for (int j = 0; j < 64; j++) acc[j] = sB[128 + j];
#pragma unroll 2
  for (int k = 0; k < 64; k++) {
    float hk = sH[k * 128 + tid];
    const float4* wr = (const float4*)(sW2 + k * 64);
#pragma unroll
    for (int jj = 0; jj < 16; jj++) {
      float4 w = wr[jj];
      acc[4 * jj + 0] = fmaf(hk, w.x, acc[4 * jj + 0]);
      acc[4 * jj + 1] = fmaf(hk, w.y, acc[4 * jj + 1]);
      acc[4 * jj + 2] = fmaf(hk, w.z, acc[4 * jj + 2]);
      acc[4 * jj + 3] = fmaf(hk, w.w, acc[4 * jj + 3]);
    }
  }

  // relu + vectorized reduction scatter into seg[dst]
  float* sg = g_seg + (size_t)d * 64;
#pragma unroll
  for (int jj = 0; jj < 16; jj++) {
    float v0 = fmaxf(acc[4 * jj + 0], 0.f);
    float v1 = fmaxf(acc[4 * jj + 1], 0.f);
    float v2 = fmaxf(acc[4 * jj + 2], 0.f);
    float v3 = fmaxf(acc[4 * jj + 3], 0.f);
    asm volatile("red.global.add.v4.f32 [%0], {%1,%2,%3,%4};"
                 :: "l"(sg + 4 * jj), "f"(v0), "f"(v1), "f"(v2), "f"(v3)
                 : "memory");
  }
  atomicAdd(&g_cnt[d], 1.0f);
}

// ---------------- K3: per-node finalize + z = relu(concat(agg,x)) @ We0 ----------------
// blockDim (128, 2): 2 nodes/block, thread j computes z[n][j]
__global__ void node_z_kernel(const float* __restrict__ x,
                              const float* __restrict__ we0) {
  __shared__ float sY[2][80];
  int n = blockIdx.x * 2 + threadIdx.y;
  int j = threadIdx.x;
  if (n < NN) {
    if (j < 64) {
      float inv = 1.f / fmaxf(g_cnt[n], 1.f);
      sY[threadIdx.y][j] = fmaxf(g_seg[n * 64 + j] * inv, 0.f);
    } else if (j < 80) {
      sY[threadIdx.y][j] = fmaxf(x[n * 16 + (j - 64)], 0.f);
    }
  }
  __syncthreads();
  if (n >= NN) return;
  float z = 0.f;
#pragma unroll 8
  for (int k = 0; k < 80; k++)
    z = fmaf(sY[threadIdx.y][k], __ldg(&we0[k * 128 + j]), z);
  g_z[(size_t)n * 128 + j] = z;
}

// ---------------- K4: per-edge output head ----------------
// 4 threads per edge, each handles 32 of the 128 dims via float4; shfl reduce.
__global__ void edge_out_kernel(const int* __restrict__ ei,
                                const float* __restrict__ bee0,
                                const float* __restrict__ we1,
                                const float* __restrict__ bee1,
                                float* __restrict__ out) {
  int t = blockIdx.x * 256 + threadIdx.x;
  int e = t >> 2;
  int l = t & 3;
  if (e >= NE) return;
  int s = ei[e];
  int d = ei[NE + e];
  const float4* zs = (const float4*)(g_z + (size_t)s * 128);
  const float4* zd = (const float4*)(g_z + (size_t)d * 128);
  const float4* bv = (const float4*)bee0;
  const float4* wv = (const float4*)we1;
  float acc = 0.f;
#pragma unroll
  for (int i = 0; i < 8; i++) {
    int idx = l * 8 + i;
    float4 a = zs[idx];
    float4 b = zd[idx];
    float4 c = __ldg(&bv[idx]);
    float4 w = __ldg(&wv[idx]);
    acc = fmaf(fmaxf(a.x - b.x + c.x, 0.f), w.x, acc);
    acc = fmaf(fmaxf(a.y - b.y + c.y, 0.f), w.y, acc);
    acc = fmaf(fmaxf(a.z - b.z + c.z, 0.f), w.z, acc);
    acc = fmaf(fmaxf(a.w - b.w + c.w, 0.f), w.w, acc);
  }
  acc += __shfl_xor_sync(0xffffffffu, acc, 1);
  acc += __shfl_xor_sync(0xffffffffu, acc, 2);
  if (l == 0) {
    float v = acc + __ldg(&bee1[0]);
    out[e] = 1.f / (1.f + __expf(-v));
  }
}

// ---------------- launch ----------------
extern "C" void kernel_launch(void* const* d_in, const int* in_sizes, int n_in,
                              void* d_out, int out_size) {
  const float* x = (const float*)d_in[0];
  const int* ei = (const int*)d_in[1];
  const float* w0 = (const float*)d_in[2];
  const float* b0 = (const float*)d_in[3];
  const float* g0 = (const float*)d_in[4];
  const float* be0 = (const float*)d_in[5];
  const float* m0 = (const float*)d_in[6];
  const float* v0 = (const float*)d_in[7];
  const float* w1 = (const float*)d_in[8];
  const float* b1 = (const float*)d_in[9];
  const float* g1 = (const float*)d_in[10];
  const float* be1 = (const float*)d_in[11];
  const float* m1 = (const float*)d_in[12];
  const float* v1 = (const float*)d_in[13];
  const float* w2 = (const float*)d_in[14];
  const float* b2 = (const float*)d_in[15];
  const float* g2 = (const float*)d_in[16];
  const float* be2 = (const float*)d_in[17];
  const float* m2 = (const float*)d_in[18];
  const float* v2 = (const float*)d_in[19];
  const float* we0 = (const float*)d_in[20];
  const float* bee0 = (const float*)d_in[21];
  const float* we1 = (const float*)d_in[22];
  const float* bee1 = (const float*)d_in[23];
  float* out = (float*)d_out;

  void* segp = nullptr;
  void* cntp = nullptr;
  cudaGetSymbolAddress(&segp, g_seg);
  cudaGetSymbolAddress(&cntp, g_cnt);
  cudaMemsetAsync(segp, 0, (size_t)NN * 64 * sizeof(float));
  cudaMemsetAsync(cntp, 0, (size_t)NN * sizeof(float));

  fold_kernel<<<1, 64>>>(w0, b0, g0, be0, m0, v0,
                         w1, b1, g1, be1, m1, v1,
                         w2, b2, g2, be2, m2, v2);

  pq_kernel<<<NN / 4, dim3(64, 4)>>>(x);

  const int smem_bytes = (4096 + 4096 + 192 + 64 * 128) * (int)sizeof(float);  // 66304
  cudaFuncSetAttribute(edge_mlp_kernel,
                       cudaFuncAttributeMaxDynamicSharedMemorySize, smem_bytes);
  edge_mlp_kernel<<<NE / 128, 128, smem_bytes>>>(ei);

  node_z_kernel<<<NN / 2, dim3(128, 2)>>>(x, we0);

  edge_out_kernel<<<NE / 64, 256>>>(ei, bee0, we1, bee1, out);
}